// round 11
// baseline (speedup 1.0000x reference)
#include <cuda_runtime.h>
#include <cuda_fp16.h>
#include <cstdint>

#define BATCH     16
#define IMG       56
#define CDIM      384
#define NHEADS    12
#define HDIM      32
#define NTOK      49
#define WIN_TOT   1024
#define M_TOT     50176
#define KDIM      384
#define NQKV      1152

#define TILE_MN   128
#define KC        64
#define NCHUNK    6
#define STAGE_BYTES 32768
#define SMEM_GEMM (3 * STAGE_BYTES)

#define NB_GATHER  (M_TOT * KDIM / 4 / 256)
#define NB_WEIGHTS ((NQKV + CDIM) * KDIM / 4 / 256)
#define NB_BM      ((4 * NHEADS * 64 * 56 + 255) / 256)

// fp16 scratch
__device__ uint4 g_xh4   [(size_t)M_TOT * KDIM  / 8];
__device__ uint4 g_qkvh4 [(size_t)M_TOT * NQKV  / 8];
__device__ uint4 g_atth4 [(size_t)M_TOT * CDIM  / 8];
__device__ uint4 g_wqkvh4[(size_t)NQKV  * KDIM  / 8];
__device__ uint4 g_wph4  [(size_t)CDIM  * KDIM  / 8];
__device__ float g_bm[4 * NHEADS * 64 * 56];

__device__ __forceinline__ uint32_t smem_u32(const void* p) {
    uint32_t a;
    asm("{ .reg .u64 t; cvta.to.shared.u64 t, %1; cvt.u32.u64 %0, t; }"
        : "=r"(a) : "l"(p));
    return a;
}

__device__ __forceinline__ int pix_offset(int m) {
    int win = m / 49;
    int tok = m - win * 49;
    int b  = win >> 6;
    int wi = win & 63;
    int wy = wi >> 3, wx = wi & 7;
    int ty = tok / 7, tx = tok - ty * 7;
    int h = wy * 7 + ty + 3; if (h >= IMG) h -= IMG;
    int w = wx * 7 + tx + 3; if (w >= IMG) w -= IMG;
    return ((b * IMG + h) * IMG + w) * CDIM;
}

#define CP_ASYNC16(dst, src) \
    asm volatile("cp.async.cg.shared.global [%0], [%1], 16;" :: "r"(dst), "l"(src))
#define CP_COMMIT() asm volatile("cp.async.commit_group;" ::: "memory")
template<int N> __device__ __forceinline__ void cp_wait() {
    asm volatile("cp.async.wait_group %0;" :: "n"(N) : "memory");
}

__device__ __forceinline__ void ldmatrix_x4(uint32_t addr, uint32_t& r0,
                                            uint32_t& r1, uint32_t& r2, uint32_t& r3) {
    asm volatile("ldmatrix.sync.aligned.m8n8.x4.shared.b16 {%0,%1,%2,%3}, [%4];"
                 : "=r"(r0), "=r"(r1), "=r"(r2), "=r"(r3) : "r"(addr));
}

__device__ __forceinline__ void ldmatrix_x4_trans(uint32_t addr, uint32_t& r0,
                                                  uint32_t& r1, uint32_t& r2, uint32_t& r3) {
    asm volatile("ldmatrix.sync.aligned.m8n8.x4.trans.shared.b16 {%0,%1,%2,%3}, [%4];"
                 : "=r"(r0), "=r"(r1), "=r"(r2), "=r"(r3) : "r"(addr));
}

__device__ __forceinline__ void mma16816(float* d, const uint32_t* a, const uint32_t* b) {
    asm volatile(
        "mma.sync.aligned.m16n8k16.row.col.f32.f16.f16.f32 "
        "{%0,%1,%2,%3}, {%4,%5,%6,%7}, {%8,%9}, {%0,%1,%2,%3};"
        : "+f"(d[0]), "+f"(d[1]), "+f"(d[2]), "+f"(d[3])
        : "r"(a[0]), "r"(a[1]), "r"(a[2]), "r"(a[3]), "r"(b[0]), "r"(b[1]));
}

__device__ __forceinline__ uint32_t packh2(float x, float y) {
    __half2 h = __floats2half2_rn(x, y);
    return *(uint32_t*)&h;
}

// ---------------------------------------------------------------------------
// Merged prologue (R10 — proven)
// ---------------------------------------------------------------------------
__global__ __launch_bounds__(256) void prep_kernel(
    const float* __restrict__ x, const float* __restrict__ wqkv,
    const float* __restrict__ wproj, const float* __restrict__ table)
{
    int bx = blockIdx.x;
    if (bx < NB_GATHER) {
        __half* dst = (__half*)g_xh4;
        int i4 = bx * 256 + threadIdx.x;
        int m  = i4 / 96, k4 = (i4 % 96) * 4;
        float4 v = *(const float4*)(x + pix_offset(m) + k4);
        __half2 h0 = __floats2half2_rn(v.x, v.y);
        __half2 h1 = __floats2half2_rn(v.z, v.w);
        *(uint2*)(dst + (size_t)m * KDIM + k4) =
            make_uint2(*(uint32_t*)&h0, *(uint32_t*)&h1);
    } else if (bx < NB_GATHER + NB_WEIGHTS) {
        int i4 = ((bx - NB_GATHER) * 256 + threadIdx.x) * 4;
        const float* s;
        __half* d;
        if (i4 < NQKV * KDIM) {
            s = wqkv + i4;
            d = (__half*)g_wqkvh4 + i4;
        } else {
            s = wproj + (i4 - NQKV * KDIM);
            d = (__half*)g_wph4 + (i4 - NQKV * KDIM);
        }
        float4 v = *(const float4*)s;
        __half2 h0 = __floats2half2_rn(v.x, v.y);
        __half2 h1 = __floats2half2_rn(v.z, v.w);
        *(uint2*)d = make_uint2(*(uint32_t*)&h0, *(uint32_t*)&h1);
    } else {
        int idx = (bx - NB_GATHER - NB_WEIGHTS) * 256 + threadIdx.x;
        if (idx >= 4 * NHEADS * 64 * 56) return;
        int j = idx % 56;
        int t = idx / 56;
        int i = t % 64; t /= 64;
        int head = t % NHEADS;
        int cls = t / NHEADS;
        float v;
        if (j < 49) {
            int ie = (i < 49) ? i : 48;
            int iy = ie / 7, ix = ie % 7, jy = j / 7, jx = j % 7;
            float bias = table[((iy - jy + 6) * 13 + (ix - jx + 6)) * NHEADS + head];
            int clsh = cls >> 1, clsw = cls & 1;
            int hi = clsh ? ((iy < 4) ? 1 : 2) : 0;
            int wi = clsw ? ((ix < 4) ? 1 : 2) : 0;
            int hj = clsh ? ((jy < 4) ? 1 : 2) : 0;
            int wj = clsw ? ((jx < 4) ? 1 : 2) : 0;
            v = bias + (((hi * 3 + wi) != (hj * 3 + wj)) ? -100.0f : 0.0f);
        } else {
            v = -1e9f;
        }
        g_bm[idx] = v;
    }
}

// ---------------------------------------------------------------------------
// fp16 GEMM (R10 — proven): 128 thr, warp tile 64x64, 3-stage cp.async
// ---------------------------------------------------------------------------
template<int OUTMODE>
__global__ __launch_bounds__(128, 2) void gemm16_kernel(
    const __half* __restrict__ A, const __half* __restrict__ W,
    const float* __restrict__ bias, void* __restrict__ Out, int ldOut)
{
    extern __shared__ __align__(128) char smem[];
    uint32_t sb = smem_u32(smem);

    int tid  = threadIdx.x;
    int lane = tid & 31, wid = tid >> 5;
    int warpM = wid >> 1, warpN = wid & 1;
    int tileM0 = blockIdx.y * TILE_MN;
    int n0 = blockIdx.x * TILE_MN;

    float acc[4][8][4] = {};

    int rowA = warpM * 64 + (lane & 15);
    int kA   = (lane >> 4) * 8;
    uint32_t xa = (uint32_t)((rowA & 7) << 4);
    int rowB = warpN * 64 + (lane & 7) + ((lane >> 4) << 3);
    int kB   = ((lane >> 3) & 1) * 8;
    uint32_t xb = (uint32_t)((rowB & 7) << 4);

    int lr = tid >> 3;
    int lc = tid & 7;

    const __half* Arow = A + (size_t)tileM0 * KDIM;
    const __half* Wrow = W + (size_t)n0 * KDIM;

    auto load_chunk = [&](int c) {
        uint32_t stage = sb + (uint32_t)((c % 3) * STAGE_BYTES);
        #pragma unroll
        for (int it = 0; it < 8; ++it) {
            int r = lr + it * 16;
            uint32_t off = ((uint32_t)(r * 128 + lc * 16)) ^ ((uint32_t)((r & 7) << 4));
            CP_ASYNC16(stage + off,          Arow + (size_t)r * KDIM + c * KC + lc * 8);
            CP_ASYNC16(stage + 16384 + off,  Wrow + (size_t)r * KDIM + c * KC + lc * 8);
        }
        CP_COMMIT();
    };

    load_chunk(0);
    load_chunk(1);

    #pragma unroll
    for (int c = 0; c < NCHUNK; ++c) {
        if (c == NCHUNK - 1) cp_wait<0>();
        else                 cp_wait<1>();
        __syncthreads();
        if (c + 2 < NCHUNK) load_chunk(c + 2);

        uint32_t sA = sb + (uint32_t)((c % 3) * STAGE_BYTES);
        uint32_t sB = sA + 16384;
        #pragma unroll
        for (int ks = 0; ks < 4; ++ks) {
            uint32_t a[4][4], b[8][2];
            #pragma unroll
            for (int mt = 0; mt < 4; ++mt) {
                uint32_t addr = sA + ((uint32_t)((rowA + mt * 16) * 128 + ks * 32 + kA * 2) ^ xa);
                ldmatrix_x4(addr, a[mt][0], a[mt][1], a[mt][2], a[mt][3]);
            }
            #pragma unroll
            for (int p = 0; p < 4; ++p) {
                uint32_t addr = sB + ((uint32_t)((rowB + p * 16) * 128 + ks * 32 + kB * 2) ^ xb);
                uint32_t r0, r1, r2, r3;
                ldmatrix_x4(addr, r0, r1, r2, r3);
                b[2 * p][0] = r0;     b[2 * p][1] = r1;
                b[2 * p + 1][0] = r2; b[2 * p + 1][1] = r3;
            }
            #pragma unroll
            for (int mt = 0; mt < 4; ++mt)
                #pragma unroll
                for (int nt = 0; nt < 8; ++nt)
                    mma16816(acc[mt][nt], a[mt], b[nt]);
        }
    }

    #pragma unroll
    for (int mt = 0; mt < 4; ++mt) {
        int m = tileM0 + warpM * 64 + mt * 16 + (lane >> 2);
        if (OUTMODE == 0) {
            __half* o0 = (__half*)Out + (size_t)m * ldOut;
            __half* o1 = (__half*)Out + (size_t)(m + 8) * ldOut;
            #pragma unroll
            for (int nt = 0; nt < 8; ++nt) {
                int n = n0 + warpN * 64 + nt * 8 + (lane & 3) * 2;
                float bx = __ldg(bias + n), by = __ldg(bias + n + 1);
                *(__half2*)(o0 + n) =
                    __floats2half2_rn(acc[mt][nt][0] + bx, acc[mt][nt][1] + by);
                *(__half2*)(o1 + n) =
                    __floats2half2_rn(acc[mt][nt][2] + bx, acc[mt][nt][3] + by);
            }
        } else {
            float* o0 = (float*)Out + pix_offset(m);
            float* o1 = (float*)Out + pix_offset(m + 8);
            #pragma unroll
            for (int nt = 0; nt < 8; ++nt) {
                int n = n0 + warpN * 64 + nt * 8 + (lane & 3) * 2;
                float bx = __ldg(bias + n), by = __ldg(bias + n + 1);
                *(float2*)(o0 + n) =
                    make_float2(acc[mt][nt][0] + bx, acc[mt][nt][1] + by);
                *(float2*)(o1 + n) =
                    make_float2(acc[mt][nt][2] + bx, acc[mt][nt][3] + by);
            }
        }
    }
}

// ---------------------------------------------------------------------------
// Tensor-core attention, TWO windows per block (256 threads, 8 warps).
// Warps 0-3 -> window 2p, warps 4-7 -> window 2p+1. Coalesced 98-row load.
// ---------------------------------------------------------------------------
#define QK_STRIDE 40

__global__ __launch_bounds__(256) void attn_mma_kernel()
{
    __shared__ __align__(16) __half Qs[128 * QK_STRIDE];
    __shared__ __align__(16) __half Ks[128 * QK_STRIDE];
    __shared__ __align__(16) __half Vs[128 * QK_STRIDE];

    int head = blockIdx.x;
    int wpair = blockIdx.y;
    int tid  = threadIdx.x;
    int lane = tid & 31, wid = tid >> 5;
    int wwin = wid >> 2;                 // 0 or 1: which window this warp owns
    int wid4 = wid & 3;

    const __half* qkvh = (const __half*)g_qkvh4;
    size_t base0 = (size_t)(wpair * 2) * NTOK * NQKV + head * HDIM;

    const __half2 sc2 = __floats2half2_rn(0.17677669529663687f, 0.17677669529663687f);
    // 128 logical rows (2 windows x 64), 4 chunks of 8 halves each = 512 slots
    #pragma unroll
    for (int f = tid; f < 512; f += 256) {
        int r = f >> 2, c = f & 3;       // r: 0..127
        int wl = r >> 6, rl = r & 63;    // window-local
        uint4 qv = make_uint4(0, 0, 0, 0), kv = qv, vv = qv;
        if (rl < NTOK) {
            const __half* p = qkvh + base0 + (size_t)(wl * NTOK + rl) * NQKV + c * 8;
            qv = *(const uint4*)p;
            kv = *(const uint4*)(p + 384);
            vv = *(const uint4*)(p + 768);
            __half2* qh = (__half2*)&qv;
            #pragma unroll
            for (int t = 0; t < 4; ++t) qh[t] = __hmul2(qh[t], sc2);
        }
        *(uint4*)&Qs[r * QK_STRIDE + c * 8] = qv;
        *(uint4*)&Ks[r * QK_STRIDE + c * 8] = kv;
        *(uint4*)&Vs[r * QK_STRIDE + c * 8] = vv;
    }
    __syncthreads();

    uint32_t woff = (uint32_t)(wwin * 64 * QK_STRIDE * 2);   // byte offset
    uint32_t sQ = smem_u32(Qs) + woff;
    uint32_t sK = smem_u32(Ks) + woff;
    uint32_t sV = smem_u32(Vs) + woff;

    int gid = lane >> 2, tig = lane & 3;
    int rowbase = wid4 * 16;

    float s[7][4] = {};
    int aRow = rowbase + (lane & 15);
    int aK   = (lane >> 4) * 8;
    int bRow = (lane & 7) + ((lane >> 4) << 3);
    int bK   = ((lane >> 3) & 1) * 8;
    #pragma unroll
    for (int ks = 0; ks < 2; ++ks) {
        uint32_t a[4];
        ldmatrix_x4(sQ + (uint32_t)(aRow * QK_STRIDE + ks * 16 + aK) * 2,
                    a[0], a[1], a[2], a[3]);
        #pragma unroll
        for (int p = 0; p < 4; ++p) {
            uint32_t r0, r1, r2, r3;
            ldmatrix_x4(sK + (uint32_t)((p * 16 + bRow) * QK_STRIDE + ks * 16 + bK) * 2,
                        r0, r1, r2, r3);
            uint32_t b0[2] = {r0, r1}, b1[2] = {r2, r3};
            mma16816(s[2 * p], a, b0);
            if (p < 3) mma16816(s[2 * p + 1], a, b1);
        }
    }

    int win = wpair * 2 + wwin;
    int r0 = rowbase + gid, r1 = r0 + 8;
    int wy = (win & 63) >> 3, wx = win & 7;
    int cls = ((wy == 7) ? 2 : 0) + ((wx == 7) ? 1 : 0);
    const float* bmBase = g_bm + (size_t)(cls * NHEADS + head) * 64 * 56;
    const float* bm0 = bmBase + r0 * 56 + tig * 2;
    const float* bm1 = bmBase + r1 * 56 + tig * 2;
    #pragma unroll
    for (int n = 0; n < 7; ++n) {
        float2 b0 = *(const float2*)(bm0 + n * 8);
        float2 b1 = *(const float2*)(bm1 + n * 8);
        s[n][0] += b0.x; s[n][1] += b0.y;
        s[n][2] += b1.x; s[n][3] += b1.y;
    }

    float mx0 = -1e30f, mx1 = -1e30f;
    #pragma unroll
    for (int n = 0; n < 7; ++n) {
        mx0 = fmaxf(mx0, fmaxf(s[n][0], s[n][1]));
        mx1 = fmaxf(mx1, fmaxf(s[n][2], s[n][3]));
    }
    mx0 = fmaxf(mx0, __shfl_xor_sync(0xffffffffu, mx0, 1));
    mx0 = fmaxf(mx0, __shfl_xor_sync(0xffffffffu, mx0, 2));
    mx1 = fmaxf(mx1, __shfl_xor_sync(0xffffffffu, mx1, 1));
    mx1 = fmaxf(mx1, __shfl_xor_sync(0xffffffffu, mx1, 2));

    float sm0 = 0.f, sm1 = 0.f;
    #pragma unroll
    for (int n = 0; n < 7; ++n) {
        s[n][0] = __expf(s[n][0] - mx0); sm0 += s[n][0];
        s[n][1] = __expf(s[n][1] - mx0); sm0 += s[n][1];
        s[n][2] = __expf(s[n][2] - mx1); sm1 += s[n][2];
        s[n][3] = __expf(s[n][3] - mx1); sm1 += s[n][3];
    }
    sm0 += __shfl_xor_sync(0xffffffffu, sm0, 1);
    sm0 += __shfl_xor_sync(0xffffffffu, sm0, 2);
    sm1 += __shfl_xor_sync(0xffffffffu, sm1, 1);
    sm1 += __shfl_xor_sync(0xffffffffu, sm1, 2);
    float inv0 = 1.0f / sm0, inv1 = 1.0f / sm1;

    uint32_t aP[4][4];
    #pragma unroll
    for (int kt = 0; kt < 4; ++kt) {
        aP[kt][0] = packh2(s[2 * kt][0], s[2 * kt][1]);
        aP[kt][1] = packh2(s[2 * kt][2], s[2 * kt][3]);
        if (kt < 3) {
            aP[kt][2] = packh2(s[2 * kt + 1][0], s[2 * kt + 1][1]);
            aP[kt][3] = packh2(s[2 * kt + 1][2], s[2 * kt + 1][3]);
        } else {
            aP[kt][2] = 0; aP[kt][3] = 0;
        }
    }

    float o[4][4] = {};
    int vRow = lane & 15;
    int vCol = (lane >> 4) << 3;
    #pragma unroll
    for (int kt = 0; kt < 4; ++kt) {
        #pragma unroll
        for (int np = 0; np < 2; ++np) {
            uint32_t r0v, r1v, r2v, r3v;
            uint32_t addr = sV + (uint32_t)((kt * 16 + vRow) * QK_STRIDE + np * 16 + vCol) * 2;
            ldmatrix_x4_trans(addr, r0v, r1v, r2v, r3v);
            uint32_t b0[2] = {r0v, r1v}, b1[2] = {r2v, r3v};
            mma16816(o[2 * np], aP[kt], b0);
            mma16816(o[2 * np + 1], aP[kt], b1);
        }
    }

    __half* att = (__half*)g_atth4;
    #pragma unroll
    for (int nt = 0; nt < 4; ++nt) {
        int col = head * HDIM + nt * 8 + tig * 2;
        if (r0 < NTOK)
            *(__half2*)(att + (size_t)(win * NTOK + r0) * CDIM + col) =
                __floats2half2_rn(o[nt][0] * inv0, o[nt][1] * inv0);
        if (r1 < NTOK)
            *(__half2*)(att + (size_t)(win * NTOK + r1) * CDIM + col) =
                __floats2half2_rn(o[nt][2] * inv1, o[nt][3] * inv1);
    }
}

extern "C" void kernel_launch(void* const* d_in, const int* in_sizes, int n_in,
                              void* d_out, int out_size) {
    const float* x     = (const float*)d_in[0];
    const float* wqkv  = (const float*)d_in[1];
    const float* bqkv  = (const float*)d_in[2];
    const float* wproj = (const float*)d_in[3];
    const float* bproj = (const float*)d_in[4];
    const float* table = (const float*)d_in[5];
    float* out = (float*)d_out;

    __half *xh, *qkvh, *atth, *wqkvh, *wph;
    cudaGetSymbolAddress((void**)&xh,    g_xh4);
    cudaGetSymbolAddress((void**)&qkvh,  g_qkvh4);
    cudaGetSymbolAddress((void**)&atth,  g_atth4);
    cudaGetSymbolAddress((void**)&wqkvh, g_wqkvh4);
    cudaGetSymbolAddress((void**)&wph,   g_wph4);

    cudaFuncSetAttribute(gemm16_kernel<0>,
                         cudaFuncAttributeMaxDynamicSharedMemorySize, SMEM_GEMM);
    cudaFuncSetAttribute(gemm16_kernel<1>,
                         cudaFuncAttributeMaxDynamicSharedMemorySize, SMEM_GEMM);

    prep_kernel<<<NB_GATHER + NB_WEIGHTS + NB_BM, 256>>>(x, wqkv, wproj, table);

    gemm16_kernel<0><<<dim3(NQKV / TILE_MN, M_TOT / TILE_MN), 128, SMEM_GEMM>>>(
        xh, wqkvh, bqkv, qkvh, NQKV);
    attn_mma_kernel<<<dim3(NHEADS, WIN_TOT / 2), 256>>>();
    gemm16_kernel<1><<<dim3(CDIM / TILE_MN, M_TOT / TILE_MN), 128, SMEM_GEMM>>>(
        atth, wph, bproj, out, 0);
}

// round 12
// speedup vs baseline: 1.1103x; 1.1103x over previous
#include <cuda_runtime.h>
#include <cuda_fp16.h>
#include <cstdint>

#define BATCH     16
#define IMG       56
#define CDIM      384
#define NHEADS    12
#define HDIM      32
#define NTOK      49
#define WIN_TOT   1024
#define M_TOT     50176
#define KDIM      384
#define NQKV      1152

#define TILE_MN   128
#define KC        64
#define NCHUNK    6
#define STAGE_BYTES 32768
#define SMEM_GEMM (3 * STAGE_BYTES)

#define NB_GATHER  (M_TOT * KDIM / 8 / 256)            // 9408 (16B/thread)
#define NB_WEIGHTS ((NQKV + CDIM) * KDIM / 4 / 256)    // 576
#define NB_BM      ((4 * NHEADS * 64 * 56 + 255) / 256) // 672

// fp16 scratch
__device__ uint4 g_xh4   [(size_t)M_TOT * KDIM  / 8];
__device__ uint4 g_qkvh4 [(size_t)M_TOT * NQKV  / 8];
__device__ uint4 g_atth4 [(size_t)M_TOT * CDIM  / 8];
__device__ uint4 g_wqkvh4[(size_t)NQKV  * KDIM  / 8];
__device__ uint4 g_wph4  [(size_t)CDIM  * KDIM  / 8];
__device__ float g_bm[4 * NHEADS * 64 * 56];

__device__ __forceinline__ uint32_t smem_u32(const void* p) {
    uint32_t a;
    asm("{ .reg .u64 t; cvta.to.shared.u64 t, %1; cvt.u32.u64 %0, t; }"
        : "=r"(a) : "l"(p));
    return a;
}

__device__ __forceinline__ int pix_offset(int m) {
    int win = m / 49;
    int tok = m - win * 49;
    int b  = win >> 6;
    int wi = win & 63;
    int wy = wi >> 3, wx = wi & 7;
    int ty = tok / 7, tx = tok - ty * 7;
    int h = wy * 7 + ty + 3; if (h >= IMG) h -= IMG;
    int w = wx * 7 + tx + 3; if (w >= IMG) w -= IMG;
    return ((b * IMG + h) * IMG + w) * CDIM;
}

#define CP_ASYNC16(dst, src) \
    asm volatile("cp.async.cg.shared.global [%0], [%1], 16;" :: "r"(dst), "l"(src))
#define CP_COMMIT() asm volatile("cp.async.commit_group;" ::: "memory")
template<int N> __device__ __forceinline__ void cp_wait() {
    asm volatile("cp.async.wait_group %0;" :: "n"(N) : "memory");
}

__device__ __forceinline__ void ldmatrix_x4(uint32_t addr, uint32_t& r0,
                                            uint32_t& r1, uint32_t& r2, uint32_t& r3) {
    asm volatile("ldmatrix.sync.aligned.m8n8.x4.shared.b16 {%0,%1,%2,%3}, [%4];"
                 : "=r"(r0), "=r"(r1), "=r"(r2), "=r"(r3) : "r"(addr));
}

__device__ __forceinline__ void ldmatrix_x4_trans(uint32_t addr, uint32_t& r0,
                                                  uint32_t& r1, uint32_t& r2, uint32_t& r3) {
    asm volatile("ldmatrix.sync.aligned.m8n8.x4.trans.shared.b16 {%0,%1,%2,%3}, [%4];"
                 : "=r"(r0), "=r"(r1), "=r"(r2), "=r"(r3) : "r"(addr));
}

__device__ __forceinline__ void mma16816(float* d, const uint32_t* a, const uint32_t* b) {
    asm volatile(
        "mma.sync.aligned.m16n8k16.row.col.f32.f16.f16.f32 "
        "{%0,%1,%2,%3}, {%4,%5,%6,%7}, {%8,%9}, {%0,%1,%2,%3};"
        : "+f"(d[0]), "+f"(d[1]), "+f"(d[2]), "+f"(d[3])
        : "r"(a[0]), "r"(a[1]), "r"(a[2]), "r"(a[3]), "r"(b[0]), "r"(b[1]));
}

__device__ __forceinline__ uint32_t packh2(float x, float y) {
    __half2 h = __floats2half2_rn(x, y);
    return *(uint32_t*)&h;
}

// ---------------------------------------------------------------------------
// Merged prologue; x gather now 16B per thread
// ---------------------------------------------------------------------------
__global__ __launch_bounds__(256) void prep_kernel(
    const float* __restrict__ x, const float* __restrict__ wqkv,
    const float* __restrict__ wproj, const float* __restrict__ table)
{
    int bx = blockIdx.x;
    if (bx < NB_GATHER) {
        __half* dst = (__half*)g_xh4;
        int i8 = bx * 256 + threadIdx.x;          // 8 elems each
        int m  = i8 / 48, k8 = (i8 % 48) * 8;
        const float* src = x + pix_offset(m) + k8;
        float4 v0 = *(const float4*)src;
        float4 v1 = *(const float4*)(src + 4);
        __half2 h0 = __floats2half2_rn(v0.x, v0.y);
        __half2 h1 = __floats2half2_rn(v0.z, v0.w);
        __half2 h2 = __floats2half2_rn(v1.x, v1.y);
        __half2 h3 = __floats2half2_rn(v1.z, v1.w);
        *(uint4*)(dst + (size_t)m * KDIM + k8) =
            make_uint4(*(uint32_t*)&h0, *(uint32_t*)&h1,
                       *(uint32_t*)&h2, *(uint32_t*)&h3);
    } else if (bx < NB_GATHER + NB_WEIGHTS) {
        int i4 = ((bx - NB_GATHER) * 256 + threadIdx.x) * 4;
        const float* s;
        __half* d;
        if (i4 < NQKV * KDIM) {
            s = wqkv + i4;
            d = (__half*)g_wqkvh4 + i4;
        } else {
            s = wproj + (i4 - NQKV * KDIM);
            d = (__half*)g_wph4 + (i4 - NQKV * KDIM);
        }
        float4 v = *(const float4*)s;
        __half2 h0 = __floats2half2_rn(v.x, v.y);
        __half2 h1 = __floats2half2_rn(v.z, v.w);
        *(uint2*)d = make_uint2(*(uint32_t*)&h0, *(uint32_t*)&h1);
    } else {
        int idx = (bx - NB_GATHER - NB_WEIGHTS) * 256 + threadIdx.x;
        if (idx >= 4 * NHEADS * 64 * 56) return;
        int j = idx % 56;
        int t = idx / 56;
        int i = t % 64; t /= 64;
        int head = t % NHEADS;
        int cls = t / NHEADS;
        float v;
        if (j < 49) {
            int ie = (i < 49) ? i : 48;
            int iy = ie / 7, ix = ie % 7, jy = j / 7, jx = j % 7;
            float bias = table[((iy - jy + 6) * 13 + (ix - jx + 6)) * NHEADS + head];
            int clsh = cls >> 1, clsw = cls & 1;
            int hi = clsh ? ((iy < 4) ? 1 : 2) : 0;
            int wi = clsw ? ((ix < 4) ? 1 : 2) : 0;
            int hj = clsh ? ((jy < 4) ? 1 : 2) : 0;
            int wj = clsw ? ((jx < 4) ? 1 : 2) : 0;
            v = bias + (((hi * 3 + wi) != (hj * 3 + wj)) ? -100.0f : 0.0f);
        } else {
            v = -1e9f;
        }
        g_bm[idx] = v;
    }
}

// ---------------------------------------------------------------------------
// fp16 GEMM (R10 — proven): 128 thr, warp tile 64x64, 3-stage cp.async
// ---------------------------------------------------------------------------
template<int OUTMODE>
__global__ __launch_bounds__(128, 2) void gemm16_kernel(
    const __half* __restrict__ A, const __half* __restrict__ W,
    const float* __restrict__ bias, void* __restrict__ Out, int ldOut)
{
    extern __shared__ __align__(128) char smem[];
    uint32_t sb = smem_u32(smem);

    int tid  = threadIdx.x;
    int lane = tid & 31, wid = tid >> 5;
    int warpM = wid >> 1, warpN = wid & 1;
    int tileM0 = blockIdx.y * TILE_MN;
    int n0 = blockIdx.x * TILE_MN;

    float acc[4][8][4] = {};

    int rowA = warpM * 64 + (lane & 15);
    int kA   = (lane >> 4) * 8;
    uint32_t xa = (uint32_t)((rowA & 7) << 4);
    int rowB = warpN * 64 + (lane & 7) + ((lane >> 4) << 3);
    int kB   = ((lane >> 3) & 1) * 8;
    uint32_t xb = (uint32_t)((rowB & 7) << 4);

    int lr = tid >> 3;
    int lc = tid & 7;

    const __half* Arow = A + (size_t)tileM0 * KDIM;
    const __half* Wrow = W + (size_t)n0 * KDIM;

    auto load_chunk = [&](int c) {
        uint32_t stage = sb + (uint32_t)((c % 3) * STAGE_BYTES);
        #pragma unroll
        for (int it = 0; it < 8; ++it) {
            int r = lr + it * 16;
            uint32_t off = ((uint32_t)(r * 128 + lc * 16)) ^ ((uint32_t)((r & 7) << 4));
            CP_ASYNC16(stage + off,          Arow + (size_t)r * KDIM + c * KC + lc * 8);
            CP_ASYNC16(stage + 16384 + off,  Wrow + (size_t)r * KDIM + c * KC + lc * 8);
        }
        CP_COMMIT();
    };

    load_chunk(0);
    load_chunk(1);

    #pragma unroll
    for (int c = 0; c < NCHUNK; ++c) {
        if (c == NCHUNK - 1) cp_wait<0>();
        else                 cp_wait<1>();
        __syncthreads();
        if (c + 2 < NCHUNK) load_chunk(c + 2);

        uint32_t sA = sb + (uint32_t)((c % 3) * STAGE_BYTES);
        uint32_t sB = sA + 16384;
        #pragma unroll
        for (int ks = 0; ks < 4; ++ks) {
            uint32_t a[4][4], b[8][2];
            #pragma unroll
            for (int mt = 0; mt < 4; ++mt) {
                uint32_t addr = sA + ((uint32_t)((rowA + mt * 16) * 128 + ks * 32 + kA * 2) ^ xa);
                ldmatrix_x4(addr, a[mt][0], a[mt][1], a[mt][2], a[mt][3]);
            }
            #pragma unroll
            for (int p = 0; p < 4; ++p) {
                uint32_t addr = sB + ((uint32_t)((rowB + p * 16) * 128 + ks * 32 + kB * 2) ^ xb);
                uint32_t r0, r1, r2, r3;
                ldmatrix_x4(addr, r0, r1, r2, r3);
                b[2 * p][0] = r0;     b[2 * p][1] = r1;
                b[2 * p + 1][0] = r2; b[2 * p + 1][1] = r3;
            }
            #pragma unroll
            for (int mt = 0; mt < 4; ++mt)
                #pragma unroll
                for (int nt = 0; nt < 8; ++nt)
                    mma16816(acc[mt][nt], a[mt], b[nt]);
        }
    }

    #pragma unroll
    for (int mt = 0; mt < 4; ++mt) {
        int m = tileM0 + warpM * 64 + mt * 16 + (lane >> 2);
        if (OUTMODE == 0) {
            __half* o0 = (__half*)Out + (size_t)m * ldOut;
            __half* o1 = (__half*)Out + (size_t)(m + 8) * ldOut;
            #pragma unroll
            for (int nt = 0; nt < 8; ++nt) {
                int n = n0 + warpN * 64 + nt * 8 + (lane & 3) * 2;
                float bx = __ldg(bias + n), by = __ldg(bias + n + 1);
                *(__half2*)(o0 + n) =
                    __floats2half2_rn(acc[mt][nt][0] + bx, acc[mt][nt][1] + by);
                *(__half2*)(o1 + n) =
                    __floats2half2_rn(acc[mt][nt][2] + bx, acc[mt][nt][3] + by);
            }
        } else {
            float* o0 = (float*)Out + pix_offset(m);
            float* o1 = (float*)Out + pix_offset(m + 8);
            #pragma unroll
            for (int nt = 0; nt < 8; ++nt) {
                int n = n0 + warpN * 64 + nt * 8 + (lane & 3) * 2;
                float bx = __ldg(bias + n), by = __ldg(bias + n + 1);
                *(float2*)(o0 + n) =
                    make_float2(acc[mt][nt][0] + bx, acc[mt][nt][1] + by);
                *(float2*)(o1 + n) =
                    make_float2(acc[mt][nt][2] + bx, acc[mt][nt][3] + by);
            }
        }
    }
}

// ---------------------------------------------------------------------------
// Tensor-core attention (R10 — proven): single window, 128 threads
// ---------------------------------------------------------------------------
#define QK_STRIDE 40

__global__ __launch_bounds__(128) void attn_mma_kernel()
{
    __shared__ __align__(16) __half Qs[64 * QK_STRIDE];
    __shared__ __align__(16) __half Ks[64 * QK_STRIDE];
    __shared__ __align__(16) __half Vs[64 * QK_STRIDE];

    int head = blockIdx.x;
    int win  = blockIdx.y;
    int tid  = threadIdx.x;
    int lane = tid & 31, wid = tid >> 5;

    const __half* qkvh = (const __half*)g_qkvh4;
    size_t base = (size_t)win * NTOK * NQKV + head * HDIM;

    const __half2 sc2 = __floats2half2_rn(0.17677669529663687f, 0.17677669529663687f);
    #pragma unroll
    for (int f = tid; f < 256; f += 128) {
        int r = f >> 2, c = f & 3;
        uint4 qv = make_uint4(0, 0, 0, 0), kv = qv, vv = qv;
        if (r < NTOK) {
            const __half* p = qkvh + base + (size_t)r * NQKV + c * 8;
            qv = *(const uint4*)p;
            kv = *(const uint4*)(p + 384);
            vv = *(const uint4*)(p + 768);
            __half2* qh = (__half2*)&qv;
            #pragma unroll
            for (int t = 0; t < 4; ++t) qh[t] = __hmul2(qh[t], sc2);
        }
        *(uint4*)&Qs[r * QK_STRIDE + c * 8] = qv;
        *(uint4*)&Ks[r * QK_STRIDE + c * 8] = kv;
        *(uint4*)&Vs[r * QK_STRIDE + c * 8] = vv;
    }
    __syncthreads();

    uint32_t sQ = smem_u32(Qs), sK = smem_u32(Ks), sV = smem_u32(Vs);

    int gid = lane >> 2, tig = lane & 3;
    int rowbase = wid * 16;

    float s[7][4] = {};
    int aRow = rowbase + (lane & 15);
    int aK   = (lane >> 4) * 8;
    int bRow = (lane & 7) + ((lane >> 4) << 3);
    int bK   = ((lane >> 3) & 1) * 8;
    #pragma unroll
    for (int ks = 0; ks < 2; ++ks) {
        uint32_t a[4];
        ldmatrix_x4(sQ + (uint32_t)(aRow * QK_STRIDE + ks * 16 + aK) * 2,
                    a[0], a[1], a[2], a[3]);
        #pragma unroll
        for (int p = 0; p < 4; ++p) {
            uint32_t r0, r1, r2, r3;
            ldmatrix_x4(sK + (uint32_t)((p * 16 + bRow) * QK_STRIDE + ks * 16 + bK) * 2,
                        r0, r1, r2, r3);
            uint32_t b0[2] = {r0, r1}, b1[2] = {r2, r3};
            mma16816(s[2 * p], a, b0);
            if (p < 3) mma16816(s[2 * p + 1], a, b1);
        }
    }

    int r0 = rowbase + gid, r1 = r0 + 8;
    int wy = (win & 63) >> 3, wx = win & 7;
    int cls = ((wy == 7) ? 2 : 0) + ((wx == 7) ? 1 : 0);
    const float* bmBase = g_bm + (size_t)(cls * NHEADS + head) * 64 * 56;
    const float* bm0 = bmBase + r0 * 56 + tig * 2;
    const float* bm1 = bmBase + r1 * 56 + tig * 2;
    #pragma unroll
    for (int n = 0; n < 7; ++n) {
        float2 b0 = *(const float2*)(bm0 + n * 8);
        float2 b1 = *(const float2*)(bm1 + n * 8);
        s[n][0] += b0.x; s[n][1] += b0.y;
        s[n][2] += b1.x; s[n][3] += b1.y;
    }

    float mx0 = -1e30f, mx1 = -1e30f;
    #pragma unroll
    for (int n = 0; n < 7; ++n) {
        mx0 = fmaxf(mx0, fmaxf(s[n][0], s[n][1]));
        mx1 = fmaxf(mx1, fmaxf(s[n][2], s[n][3]));
    }
    mx0 = fmaxf(mx0, __shfl_xor_sync(0xffffffffu, mx0, 1));
    mx0 = fmaxf(mx0, __shfl_xor_sync(0xffffffffu, mx0, 2));
    mx1 = fmaxf(mx1, __shfl_xor_sync(0xffffffffu, mx1, 1));
    mx1 = fmaxf(mx1, __shfl_xor_sync(0xffffffffu, mx1, 2));

    float sm0 = 0.f, sm1 = 0.f;
    #pragma unroll
    for (int n = 0; n < 7; ++n) {
        s[n][0] = __expf(s[n][0] - mx0); sm0 += s[n][0];
        s[n][1] = __expf(s[n][1] - mx0); sm0 += s[n][1];
        s[n][2] = __expf(s[n][2] - mx1); sm1 += s[n][2];
        s[n][3] = __expf(s[n][3] - mx1); sm1 += s[n][3];
    }
    sm0 += __shfl_xor_sync(0xffffffffu, sm0, 1);
    sm0 += __shfl_xor_sync(0xffffffffu, sm0, 2);
    sm1 += __shfl_xor_sync(0xffffffffu, sm1, 1);
    sm1 += __shfl_xor_sync(0xffffffffu, sm1, 2);
    float inv0 = 1.0f / sm0, inv1 = 1.0f / sm1;

    uint32_t aP[4][4];
    #pragma unroll
    for (int kt = 0; kt < 4; ++kt) {
        aP[kt][0] = packh2(s[2 * kt][0], s[2 * kt][1]);
        aP[kt][1] = packh2(s[2 * kt][2], s[2 * kt][3]);
        if (kt < 3) {
            aP[kt][2] = packh2(s[2 * kt + 1][0], s[2 * kt + 1][1]);
            aP[kt][3] = packh2(s[2 * kt + 1][2], s[2 * kt + 1][3]);
        } else {
            aP[kt][2] = 0; aP[kt][3] = 0;
        }
    }

    float o[4][4] = {};
    int vRow = lane & 15;
    int vCol = (lane >> 4) << 3;
    #pragma unroll
    for (int kt = 0; kt < 4; ++kt) {
        #pragma unroll
        for (int np = 0; np < 2; ++np) {
            uint32_t r0v, r1v, r2v, r3v;
            uint32_t addr = sV + (uint32_t)((kt * 16 + vRow) * QK_STRIDE + np * 16 + vCol) * 2;
            ldmatrix_x4_trans(addr, r0v, r1v, r2v, r3v);
            uint32_t b0[2] = {r0v, r1v}, b1[2] = {r2v, r3v};
            mma16816(o[2 * np], aP[kt], b0);
            mma16816(o[2 * np + 1], aP[kt], b1);
        }
    }

    __half* att = (__half*)g_atth4;
    #pragma unroll
    for (int nt = 0; nt < 4; ++nt) {
        int col = head * HDIM + nt * 8 + tig * 2;
        if (r0 < NTOK)
            *(__half2*)(att + (size_t)(win * NTOK + r0) * CDIM + col) =
                __floats2half2_rn(o[nt][0] * inv0, o[nt][1] * inv0);
        if (r1 < NTOK)
            *(__half2*)(att + (size_t)(win * NTOK + r1) * CDIM + col) =
                __floats2half2_rn(o[nt][2] * inv1, o[nt][3] * inv1);
    }
}

extern "C" void kernel_launch(void* const* d_in, const int* in_sizes, int n_in,
                              void* d_out, int out_size) {
    const float* x     = (const float*)d_in[0];
    const float* wqkv  = (const float*)d_in[1];
    const float* bqkv  = (const float*)d_in[2];
    const float* wproj = (const float*)d_in[3];
    const float* bproj = (const float*)d_in[4];
    const float* table = (const float*)d_in[5];
    float* out = (float*)d_out;

    __half *xh, *qkvh, *atth, *wqkvh, *wph;
    cudaGetSymbolAddress((void**)&xh,    g_xh4);
    cudaGetSymbolAddress((void**)&qkvh,  g_qkvh4);
    cudaGetSymbolAddress((void**)&atth,  g_atth4);
    cudaGetSymbolAddress((void**)&wqkvh, g_wqkvh4);
    cudaGetSymbolAddress((void**)&wph,   g_wph4);

    cudaFuncSetAttribute(gemm16_kernel<0>,
                         cudaFuncAttributeMaxDynamicSharedMemorySize, SMEM_GEMM);
    cudaFuncSetAttribute(gemm16_kernel<1>,
                         cudaFuncAttributeMaxDynamicSharedMemorySize, SMEM_GEMM);

    prep_kernel<<<NB_GATHER + NB_WEIGHTS + NB_BM, 256>>>(x, wqkv, wproj, table);

    gemm16_kernel<0><<<dim3(NQKV / TILE_MN, M_TOT / TILE_MN), 128, SMEM_GEMM>>>(
        xh, wqkvh, bqkv, qkvh, NQKV);
    attn_mma_kernel<<<dim3(NHEADS, WIN_TOT), 128>>>();
    gemm16_kernel<1><<<dim3(CDIM / TILE_MN, M_TOT / TILE_MN), 128, SMEM_GEMM>>>(
        atth, wph, bproj, out, 0);
}

// round 13
// speedup vs baseline: 1.1267x; 1.0148x over previous
#include <cuda_runtime.h>
#include <cuda_fp16.h>
#include <cstdint>

#define BATCH     16
#define IMG       56
#define CDIM      384
#define NHEADS    12
#define HDIM      32
#define NTOK      49
#define WIN_TOT   1024
#define M_TOT     50176
#define KDIM      384
#define NQKV      1152

#define TILE_MN   128
#define KC        64
#define NCHUNK    6
#define STAGE_BYTES 32768
#define SMEM_GEMM (3 * STAGE_BYTES)

#define NB_GATHER  (M_TOT * KDIM / 8 / 256)
#define NB_WEIGHTS ((NQKV + CDIM) * KDIM / 4 / 256)
#define NB_BM      ((4 * NHEADS * 64 * 56 + 255) / 256)

#define QSCALE 0.17677669529663687f

// fp16 scratch
__device__ uint4 g_xh4   [(size_t)M_TOT * KDIM  / 8];
__device__ uint4 g_qkvh4 [(size_t)M_TOT * NQKV  / 8];
__device__ uint4 g_atth4 [(size_t)M_TOT * CDIM  / 8];
__device__ uint4 g_wqkvh4[(size_t)NQKV  * KDIM  / 8];
__device__ uint4 g_wph4  [(size_t)CDIM  * KDIM  / 8];
__device__ float g_bm[4 * NHEADS * 64 * 56];

__device__ __forceinline__ uint32_t smem_u32(const void* p) {
    uint32_t a;
    asm("{ .reg .u64 t; cvta.to.shared.u64 t, %1; cvt.u32.u64 %0, t; }"
        : "=r"(a) : "l"(p));
    return a;
}

__device__ __forceinline__ int pix_offset(int m) {
    int win = m / 49;
    int tok = m - win * 49;
    int b  = win >> 6;
    int wi = win & 63;
    int wy = wi >> 3, wx = wi & 7;
    int ty = tok / 7, tx = tok - ty * 7;
    int h = wy * 7 + ty + 3; if (h >= IMG) h -= IMG;
    int w = wx * 7 + tx + 3; if (w >= IMG) w -= IMG;
    return ((b * IMG + h) * IMG + w) * CDIM;
}

#define CP_ASYNC16(dst, src) \
    asm volatile("cp.async.cg.shared.global [%0], [%1], 16;" :: "r"(dst), "l"(src))
#define CP_ASYNC16Z(dst, src, sz) \
    asm volatile("cp.async.cg.shared.global [%0], [%1], 16, %2;" \
                 :: "r"(dst), "l"(src), "r"(sz))
#define CP_COMMIT() asm volatile("cp.async.commit_group;" ::: "memory")
template<int N> __device__ __forceinline__ void cp_wait() {
    asm volatile("cp.async.wait_group %0;" :: "n"(N) : "memory");
}

__device__ __forceinline__ void ldmatrix_x4(uint32_t addr, uint32_t& r0,
                                            uint32_t& r1, uint32_t& r2, uint32_t& r3) {
    asm volatile("ldmatrix.sync.aligned.m8n8.x4.shared.b16 {%0,%1,%2,%3}, [%4];"
                 : "=r"(r0), "=r"(r1), "=r"(r2), "=r"(r3) : "r"(addr));
}

__device__ __forceinline__ void ldmatrix_x4_trans(uint32_t addr, uint32_t& r0,
                                                  uint32_t& r1, uint32_t& r2, uint32_t& r3) {
    asm volatile("ldmatrix.sync.aligned.m8n8.x4.trans.shared.b16 {%0,%1,%2,%3}, [%4];"
                 : "=r"(r0), "=r"(r1), "=r"(r2), "=r"(r3) : "r"(addr));
}

__device__ __forceinline__ void mma16816(float* d, const uint32_t* a, const uint32_t* b) {
    asm volatile(
        "mma.sync.aligned.m16n8k16.row.col.f32.f16.f16.f32 "
        "{%0,%1,%2,%3}, {%4,%5,%6,%7}, {%8,%9}, {%0,%1,%2,%3};"
        : "+f"(d[0]), "+f"(d[1]), "+f"(d[2]), "+f"(d[3])
        : "r"(a[0]), "r"(a[1]), "r"(a[2]), "r"(a[3]), "r"(b[0]), "r"(b[1]));
}

__device__ __forceinline__ uint32_t packh2(float x, float y) {
    __half2 h = __floats2half2_rn(x, y);
    return *(uint32_t*)&h;
}

// ---------------------------------------------------------------------------
// Merged prologue (R12 — proven)
// ---------------------------------------------------------------------------
__global__ __launch_bounds__(256) void prep_kernel(
    const float* __restrict__ x, const float* __restrict__ wqkv,
    const float* __restrict__ wproj, const float* __restrict__ table)
{
    int bx = blockIdx.x;
    if (bx < NB_GATHER) {
        __half* dst = (__half*)g_xh4;
        int i8 = bx * 256 + threadIdx.x;
        int m  = i8 / 48, k8 = (i8 % 48) * 8;
        const float* src = x + pix_offset(m) + k8;
        float4 v0 = *(const float4*)src;
        float4 v1 = *(const float4*)(src + 4);
        __half2 h0 = __floats2half2_rn(v0.x, v0.y);
        __half2 h1 = __floats2half2_rn(v0.z, v0.w);
        __half2 h2 = __floats2half2_rn(v1.x, v1.y);
        __half2 h3 = __floats2half2_rn(v1.z, v1.w);
        *(uint4*)(dst + (size_t)m * KDIM + k8) =
            make_uint4(*(uint32_t*)&h0, *(uint32_t*)&h1,
                       *(uint32_t*)&h2, *(uint32_t*)&h3);
    } else if (bx < NB_GATHER + NB_WEIGHTS) {
        int i4 = ((bx - NB_GATHER) * 256 + threadIdx.x) * 4;
        const float* s;
        __half* d;
        if (i4 < NQKV * KDIM) {
            s = wqkv + i4;
            d = (__half*)g_wqkvh4 + i4;
        } else {
            s = wproj + (i4 - NQKV * KDIM);
            d = (__half*)g_wph4 + (i4 - NQKV * KDIM);
        }
        float4 v = *(const float4*)s;
        __half2 h0 = __floats2half2_rn(v.x, v.y);
        __half2 h1 = __floats2half2_rn(v.z, v.w);
        *(uint2*)d = make_uint2(*(uint32_t*)&h0, *(uint32_t*)&h1);
    } else {
        int idx = (bx - NB_GATHER - NB_WEIGHTS) * 256 + threadIdx.x;
        if (idx >= 4 * NHEADS * 64 * 56) return;
        int j = idx % 56;
        int t = idx / 56;
        int i = t % 64; t /= 64;
        int head = t % NHEADS;
        int cls = t / NHEADS;
        float v;
        if (j < 49) {
            int ie = (i < 49) ? i : 48;
            int iy = ie / 7, ix = ie % 7, jy = j / 7, jx = j % 7;
            float bias = table[((iy - jy + 6) * 13 + (ix - jx + 6)) * NHEADS + head];
            int clsh = cls >> 1, clsw = cls & 1;
            int hi = clsh ? ((iy < 4) ? 1 : 2) : 0;
            int wi = clsw ? ((ix < 4) ? 1 : 2) : 0;
            int hj = clsh ? ((jy < 4) ? 1 : 2) : 0;
            int wj = clsw ? ((jx < 4) ? 1 : 2) : 0;
            v = bias + (((hi * 3 + wi) != (hj * 3 + wj)) ? -100.0f : 0.0f);
        } else {
            v = -1e9f;
        }
        g_bm[idx] = v;
    }
}

// ---------------------------------------------------------------------------
// fp16 GEMM (R10/R12 — proven). OUTMODE 0 additionally scales the Q column
// block (n0 < 384) by 1/sqrt(32) in fp32 before the fp16 round.
// ---------------------------------------------------------------------------
template<int OUTMODE>
__global__ __launch_bounds__(128, 2) void gemm16_kernel(
    const __half* __restrict__ A, const __half* __restrict__ W,
    const float* __restrict__ bias, void* __restrict__ Out, int ldOut)
{
    extern __shared__ __align__(128) char smem[];
    uint32_t sb = smem_u32(smem);

    int tid  = threadIdx.x;
    int lane = tid & 31, wid = tid >> 5;
    int warpM = wid >> 1, warpN = wid & 1;
    int tileM0 = blockIdx.y * TILE_MN;
    int n0 = blockIdx.x * TILE_MN;

    float acc[4][8][4] = {};

    int rowA = warpM * 64 + (lane & 15);
    int kA   = (lane >> 4) * 8;
    uint32_t xa = (uint32_t)((rowA & 7) << 4);
    int rowB = warpN * 64 + (lane & 7) + ((lane >> 4) << 3);
    int kB   = ((lane >> 3) & 1) * 8;
    uint32_t xb = (uint32_t)((rowB & 7) << 4);

    int lr = tid >> 3;
    int lc = tid & 7;

    const __half* Arow = A + (size_t)tileM0 * KDIM;
    const __half* Wrow = W + (size_t)n0 * KDIM;

    auto load_chunk = [&](int c) {
        uint32_t stage = sb + (uint32_t)((c % 3) * STAGE_BYTES);
        #pragma unroll
        for (int it = 0; it < 8; ++it) {
            int r = lr + it * 16;
            uint32_t off = ((uint32_t)(r * 128 + lc * 16)) ^ ((uint32_t)((r & 7) << 4));
            CP_ASYNC16(stage + off,          Arow + (size_t)r * KDIM + c * KC + lc * 8);
            CP_ASYNC16(stage + 16384 + off,  Wrow + (size_t)r * KDIM + c * KC + lc * 8);
        }
        CP_COMMIT();
    };

    load_chunk(0);
    load_chunk(1);

    #pragma unroll
    for (int c = 0; c < NCHUNK; ++c) {
        if (c == NCHUNK - 1) cp_wait<0>();
        else                 cp_wait<1>();
        __syncthreads();
        if (c + 2 < NCHUNK) load_chunk(c + 2);

        uint32_t sA = sb + (uint32_t)((c % 3) * STAGE_BYTES);
        uint32_t sB = sA + 16384;
        #pragma unroll
        for (int ks = 0; ks < 4; ++ks) {
            uint32_t a[4][4], b[8][2];
            #pragma unroll
            for (int mt = 0; mt < 4; ++mt) {
                uint32_t addr = sA + ((uint32_t)((rowA + mt * 16) * 128 + ks * 32 + kA * 2) ^ xa);
                ldmatrix_x4(addr, a[mt][0], a[mt][1], a[mt][2], a[mt][3]);
            }
            #pragma unroll
            for (int p = 0; p < 4; ++p) {
                uint32_t addr = sB + ((uint32_t)((rowB + p * 16) * 128 + ks * 32 + kB * 2) ^ xb);
                uint32_t r0, r1, r2, r3;
                ldmatrix_x4(addr, r0, r1, r2, r3);
                b[2 * p][0] = r0;     b[2 * p][1] = r1;
                b[2 * p + 1][0] = r2; b[2 * p + 1][1] = r3;
            }
            #pragma unroll
            for (int mt = 0; mt < 4; ++mt)
                #pragma unroll
                for (int nt = 0; nt < 8; ++nt)
                    mma16816(acc[mt][nt], a[mt], b[nt]);
        }
    }

    float osc = (OUTMODE == 0 && n0 < CDIM) ? QSCALE : 1.0f;

    #pragma unroll
    for (int mt = 0; mt < 4; ++mt) {
        int m = tileM0 + warpM * 64 + mt * 16 + (lane >> 2);
        if (OUTMODE == 0) {
            __half* o0 = (__half*)Out + (size_t)m * ldOut;
            __half* o1 = (__half*)Out + (size_t)(m + 8) * ldOut;
            #pragma unroll
            for (int nt = 0; nt < 8; ++nt) {
                int n = n0 + warpN * 64 + nt * 8 + (lane & 3) * 2;
                float bx = __ldg(bias + n), by = __ldg(bias + n + 1);
                *(__half2*)(o0 + n) =
                    __floats2half2_rn((acc[mt][nt][0] + bx) * osc,
                                      (acc[mt][nt][1] + by) * osc);
                *(__half2*)(o1 + n) =
                    __floats2half2_rn((acc[mt][nt][2] + bx) * osc,
                                      (acc[mt][nt][3] + by) * osc);
            }
        } else {
            float* o0 = (float*)Out + pix_offset(m);
            float* o1 = (float*)Out + pix_offset(m + 8);
            #pragma unroll
            for (int nt = 0; nt < 8; ++nt) {
                int n = n0 + warpN * 64 + nt * 8 + (lane & 3) * 2;
                float bx = __ldg(bias + n), by = __ldg(bias + n + 1);
                *(float2*)(o0 + n) =
                    make_float2(acc[mt][nt][0] + bx, acc[mt][nt][1] + by);
                *(float2*)(o1 + n) =
                    make_float2(acc[mt][nt][2] + bx, acc[mt][nt][3] + by);
            }
        }
    }
}

// ---------------------------------------------------------------------------
// Tensor-core attention: Q pre-scaled by QKV epilogue; loads via cp.async
// with src-size zero-fill (no register round trip, no predicates).
// ---------------------------------------------------------------------------
#define QK_STRIDE 40
#define MAT_BYTES (64 * QK_STRIDE * 2)   // 5120 B per matrix

__global__ __launch_bounds__(128) void attn_mma_kernel()
{
    __shared__ __align__(16) __half QKV3[3 * 64 * QK_STRIDE];

    int head = blockIdx.x;
    int win  = blockIdx.y;
    int tid  = threadIdx.x;
    int lane = tid & 31, wid = tid >> 5;

    const __half* qkvh = (const __half*)g_qkvh4;
    size_t base = (size_t)win * NTOK * NQKV + head * HDIM;

    uint32_t sQ = smem_u32(QKV3);
    uint32_t sK = sQ + MAT_BYTES;
    uint32_t sV = sQ + 2 * MAT_BYTES;

    // 64 rows x 4 chunks of 16B, for Q/K/V — zero-fill rows >= 49
    #pragma unroll
    for (int f = tid; f < 256; f += 128) {
        int r = f >> 2, c = f & 3;
        int rc = (r < NTOK) ? r : 0;                 // clamp (safe address)
        uint32_t sz = (r < NTOK) ? 16u : 0u;         // src-size 0 -> zero fill
        const __half* p = qkvh + base + (size_t)rc * NQKV + c * 8;
        uint32_t d = (uint32_t)(r * (QK_STRIDE * 2) + c * 16);
        CP_ASYNC16Z(sQ + d, p,       sz);
        CP_ASYNC16Z(sK + d, p + 384, sz);
        CP_ASYNC16Z(sV + d, p + 768, sz);
    }
    CP_COMMIT();
    cp_wait<0>();
    __syncthreads();

    int gid = lane >> 2, tig = lane & 3;
    int rowbase = wid * 16;

    float s[7][4] = {};
    int aRow = rowbase + (lane & 15);
    int aK   = (lane >> 4) * 8;
    int bRow = (lane & 7) + ((lane >> 4) << 3);
    int bK   = ((lane >> 3) & 1) * 8;
    #pragma unroll
    for (int ks = 0; ks < 2; ++ks) {
        uint32_t a[4];
        ldmatrix_x4(sQ + (uint32_t)(aRow * QK_STRIDE + ks * 16 + aK) * 2,
                    a[0], a[1], a[2], a[3]);
        #pragma unroll
        for (int p = 0; p < 4; ++p) {
            uint32_t r0, r1, r2, r3;
            ldmatrix_x4(sK + (uint32_t)((p * 16 + bRow) * QK_STRIDE + ks * 16 + bK) * 2,
                        r0, r1, r2, r3);
            uint32_t b0[2] = {r0, r1}, b1[2] = {r2, r3};
            mma16816(s[2 * p], a, b0);
            if (p < 3) mma16816(s[2 * p + 1], a, b1);
        }
    }

    int r0 = rowbase + gid, r1 = r0 + 8;
    int wy = (win & 63) >> 3, wx = win & 7;
    int cls = ((wy == 7) ? 2 : 0) + ((wx == 7) ? 1 : 0);
    const float* bmBase = g_bm + (size_t)(cls * NHEADS + head) * 64 * 56;
    const float* bm0 = bmBase + r0 * 56 + tig * 2;
    const float* bm1 = bmBase + r1 * 56 + tig * 2;
    #pragma unroll
    for (int n = 0; n < 7; ++n) {
        float2 b0 = *(const float2*)(bm0 + n * 8);
        float2 b1 = *(const float2*)(bm1 + n * 8);
        s[n][0] += b0.x; s[n][1] += b0.y;
        s[n][2] += b1.x; s[n][3] += b1.y;
    }

    float mx0 = -1e30f, mx1 = -1e30f;
    #pragma unroll
    for (int n = 0; n < 7; ++n) {
        mx0 = fmaxf(mx0, fmaxf(s[n][0], s[n][1]));
        mx1 = fmaxf(mx1, fmaxf(s[n][2], s[n][3]));
    }
    mx0 = fmaxf(mx0, __shfl_xor_sync(0xffffffffu, mx0, 1));
    mx0 = fmaxf(mx0, __shfl_xor_sync(0xffffffffu, mx0, 2));
    mx1 = fmaxf(mx1, __shfl_xor_sync(0xffffffffu, mx1, 1));
    mx1 = fmaxf(mx1, __shfl_xor_sync(0xffffffffu, mx1, 2));

    float sm0 = 0.f, sm1 = 0.f;
    #pragma unroll
    for (int n = 0; n < 7; ++n) {
        s[n][0] = __expf(s[n][0] - mx0); sm0 += s[n][0];
        s[n][1] = __expf(s[n][1] - mx0); sm0 += s[n][1];
        s[n][2] = __expf(s[n][2] - mx1); sm1 += s[n][2];
        s[n][3] = __expf(s[n][3] - mx1); sm1 += s[n][3];
    }
    sm0 += __shfl_xor_sync(0xffffffffu, sm0, 1);
    sm0 += __shfl_xor_sync(0xffffffffu, sm0, 2);
    sm1 += __shfl_xor_sync(0xffffffffu, sm1, 1);
    sm1 += __shfl_xor_sync(0xffffffffu, sm1, 2);
    float inv0 = 1.0f / sm0, inv1 = 1.0f / sm1;

    uint32_t aP[4][4];
    #pragma unroll
    for (int kt = 0; kt < 4; ++kt) {
        aP[kt][0] = packh2(s[2 * kt][0], s[2 * kt][1]);
        aP[kt][1] = packh2(s[2 * kt][2], s[2 * kt][3]);
        if (kt < 3) {
            aP[kt][2] = packh2(s[2 * kt + 1][0], s[2 * kt + 1][1]);
            aP[kt][3] = packh2(s[2 * kt + 1][2], s[2 * kt + 1][3]);
        } else {
            aP[kt][2] = 0; aP[kt][3] = 0;
        }
    }

    float o[4][4] = {};
    int vRow = lane & 15;
    int vCol = (lane >> 4) << 3;
    #pragma unroll
    for (int kt = 0; kt < 4; ++kt) {
        #pragma unroll
        for (int np = 0; np < 2; ++np) {
            uint32_t r0v, r1v, r2v, r3v;
            uint32_t addr = sV + (uint32_t)((kt * 16 + vRow) * QK_STRIDE + np * 16 + vCol) * 2;
            ldmatrix_x4_trans(addr, r0v, r1v, r2v, r3v);
            uint32_t b0[2] = {r0v, r1v}, b1[2] = {r2v, r3v};
            mma16816(o[2 * np], aP[kt], b0);
            mma16816(o[2 * np + 1], aP[kt], b1);
        }
    }

    __half* att = (__half*)g_atth4;
    #pragma unroll
    for (int nt = 0; nt < 4; ++nt) {
        int col = head * HDIM + nt * 8 + tig * 2;
        if (r0 < NTOK)
            *(__half2*)(att + (size_t)(win * NTOK + r0) * CDIM + col) =
                __floats2half2_rn(o[nt][0] * inv0, o[nt][1] * inv0);
        if (r1 < NTOK)
            *(__half2*)(att + (size_t)(win * NTOK + r1) * CDIM + col) =
                __floats2half2_rn(o[nt][2] * inv1, o[nt][3] * inv1);
    }
}

extern "C" void kernel_launch(void* const* d_in, const int* in_sizes, int n_in,
                              void* d_out, int out_size) {
    const float* x     = (const float*)d_in[0];
    const float* wqkv  = (const float*)d_in[1];
    const float* bqkv  = (const float*)d_in[2];
    const float* wproj = (const float*)d_in[3];
    const float* bproj = (const float*)d_in[4];
    const float* table = (const float*)d_in[5];
    float* out = (float*)d_out;

    __half *xh, *qkvh, *atth, *wqkvh, *wph;
    cudaGetSymbolAddress((void**)&xh,    g_xh4);
    cudaGetSymbolAddress((void**)&qkvh,  g_qkvh4);
    cudaGetSymbolAddress((void**)&atth,  g_atth4);
    cudaGetSymbolAddress((void**)&wqkvh, g_wqkvh4);
    cudaGetSymbolAddress((void**)&wph,   g_wph4);

    cudaFuncSetAttribute(gemm16_kernel<0>,
                         cudaFuncAttributeMaxDynamicSharedMemorySize, SMEM_GEMM);
    cudaFuncSetAttribute(gemm16_kernel<1>,
                         cudaFuncAttributeMaxDynamicSharedMemorySize, SMEM_GEMM);

    prep_kernel<<<NB_GATHER + NB_WEIGHTS + NB_BM, 256>>>(x, wqkv, wproj, table);

    gemm16_kernel<0><<<dim3(NQKV / TILE_MN, M_TOT / TILE_MN), 128, SMEM_GEMM>>>(
        xh, wqkvh, bqkv, qkvh, NQKV);
    attn_mma_kernel<<<dim3(NHEADS, WIN_TOT), 128>>>();
    gemm16_kernel<1><<<dim3(CDIM / TILE_MN, M_TOT / TILE_MN), 128, SMEM_GEMM>>>(
        atth, wph, bproj, out, 0);
}